// round 15
// baseline (speedup 1.0000x reference)
#include <cuda_runtime.h>
#include <cuda_bf16.h>
#include <stdint.h>

#define NB    4
#define NPTS  16384
#define NCTR  1024
#define NSAMP 32
#define R2    0.04f
#define NWORK 124
#define NGRID (NB + NWORK)      // 128 blocks <= 148 SMs, 1/SM @ 226KB smem
#define NGROUP (NB * NCTR / 8)  // 512 groups of 8 centers

// ---------------- scratch (no allocations allowed) ----------------
__device__ float    g_featsT[(size_t)NB * NPTS * 64];   // (B,N,C)
__device__ unsigned g_progress[NB];

// ---------------- packed f32x2 helpers (exact per-half RN) ----------------
__device__ __forceinline__ unsigned long long pack2(float lo, float hi) {
    unsigned long long r;
    asm("mov.b64 %0, {%1, %2};" : "=l"(r) : "f"(lo), "f"(hi));
    return r;
}
__device__ __forceinline__ void unpack2(unsigned long long v, float& lo, float& hi) {
    asm("mov.b64 {%0, %1}, %2;" : "=f"(lo), "=f"(hi) : "l"(v));
}
__device__ __forceinline__ unsigned long long add2(unsigned long long a, unsigned long long b) {
    unsigned long long r;
    asm("add.rn.f32x2 %0, %1, %2;" : "=l"(r) : "l"(a), "l"(b));
    return r;
}
__device__ __forceinline__ unsigned long long mul2(unsigned long long a, unsigned long long b) {
    unsigned long long r;
    asm("mul.rn.f32x2 %0, %1, %2;" : "=l"(r) : "l"(a), "l"(b));
    return r;
}

// ---------------- layouts ----------------
#define FPS_CTRL_OFF (3 * NPTS * 4 + NPTS * 2)   // bytes
#define FPS_SMEM     (FPS_CTRL_OFF + 2048)       // 231424 B

#define BUFW 68
#define WOW1   0
#define WOW2   (WOW1 + 68 * 64)
#define WOW3   (WOW2 + 64 * 64)
#define WOSV   (WOW3 + 64 * 128)
#define WOBA   (WOSV + 512)
#define WOBB   (WOBA + 4 * 64 * BUFW)
#define WOPOOL (WOBB + 4 * 64 * BUFW)
#define WOSIDX (WOPOOL + 1024)   // 256 ints; total 53248 floats = 212992 B

__global__ void reset_kernel()
{
    if (threadIdx.x < NB) g_progress[threadIdx.x] = 0u;
}

// ---------------------------------------------------------------------------
// transpose features (B,64,N) -> (B,N,64)
// ---------------------------------------------------------------------------
__global__ void transpose_kernel(const float* __restrict__ f)
{
    __shared__ float tile[32][33];
    int n0 = blockIdx.x * 32, c0 = blockIdx.y * 32, b = blockIdx.z;
    int tx = threadIdx.x, ty = threadIdx.y;
    const float* src = f + (size_t)b * 64 * NPTS;
#pragma unroll
    for (int r = 0; r < 32; r += 8)
        tile[ty + r][tx] = src[(size_t)(c0 + ty + r) * NPTS + n0 + tx];
    __syncthreads();
    float* dst = g_featsT + (size_t)b * NPTS * 64;
#pragma unroll
    for (int r = 0; r < 32; r += 8)
        dst[(size_t)(n0 + ty + r) * 64 + c0 + tx] = tile[tx][ty + r];
}

// ---------------------------------------------------------------------------
// Fused persistent kernel:
//   blocks 0..3   : FPS (1 per batch) + release-store progress every 8 ctrs
//   blocks 4..127 : per-group {acquire-spin, ballquery, MLP, pool, store}
// FPS reduction: lane0 STS64 warp key -> bar1 -> warp0 derives global winner
// and STS128-publishes coords -> bar2 -> all warps LDS128 (1 MIO op each).
// Single-buffered: iteration k+1's slot writes happen after bar2, so warp0's
// reads between bar1/bar2 can never race them. No hang paths: FPS never waits
// on workers; workers' spin targets monotonically-increasing progress.
// ---------------------------------------------------------------------------
__global__ void __launch_bounds__(1024, 1)
fused_kernel(const float* __restrict__ xyz,
             const float* __restrict__ W1, const float* __restrict__ s1, const float* __restrict__ b1,
             const float* __restrict__ W2, const float* __restrict__ s2, const float* __restrict__ b2,
             const float* __restrict__ W3, const float* __restrict__ s3, const float* __restrict__ b3,
             float* __restrict__ out)
{
    extern __shared__ float sm[];
    const int t = threadIdx.x;

    if (blockIdx.x < NB) {
        // ================= FPS path =================
        float* shx = sm;
        float* shy = sm + NPTS;
        float* shz = sm + 2 * NPTS;
        uint16_t* sp16 = (uint16_t*)(sm + 3 * NPTS);
        unsigned int* ctrl = (unsigned int*)((char*)sm + FPS_CTRL_OFF);
        unsigned int* hist = ctrl;                                 // setup only
        unsigned long long* wkey = (unsigned long long*)ctrl;      // [32] aliases hist
        float4* s_win = (float4*)(ctrl + 64);                      // 16B aligned

        const int tid = t;
        const int b = blockIdx.x;
        const float* xb = xyz + (size_t)b * NPTS * 3;
        float* outx = out + (size_t)b * NCTR * 3;

        if (tid < 512) hist[tid] = 0u;
        __syncthreads();
        for (int p = tid; p < NPTS; p += 1024) {
            float x = xb[3 * p], y = xb[3 * p + 1], z = xb[3 * p + 2];
            int cx = min(7, (int)(x * 8.0f));
            int cy = min(7, (int)(y * 8.0f));
            int cz = min(7, (int)(z * 8.0f));
            atomicAdd(&hist[(cx << 6) | (cy << 3) | cz], 1u);
        }
        __syncthreads();
        if (tid < 32) {
            unsigned v[16], s = 0;
#pragma unroll
            for (int i = 0; i < 16; i++) { v[i] = hist[tid * 16 + i]; s += v[i]; }
            unsigned run = s;
#pragma unroll
            for (int o = 1; o < 32; o <<= 1) {
                unsigned t2 = __shfl_up_sync(0xffffffffu, run, o);
                if (tid >= o) run += t2;
            }
            unsigned acc = run - s;
#pragma unroll
            for (int i = 0; i < 16; i++) { unsigned c = v[i]; hist[tid * 16 + i] = acc; acc += c; }
        }
        __syncthreads();
        for (int p = tid; p < NPTS; p += 1024) {
            float x = xb[3 * p], y = xb[3 * p + 1], z = xb[3 * p + 2];
            int cx = min(7, (int)(x * 8.0f));
            int cy = min(7, (int)(y * 8.0f));
            int cz = min(7, (int)(z * 8.0f));
            unsigned pos = atomicAdd(&hist[(cx << 6) | (cy << 3) | cz], 1u);
            shx[pos] = x; shy[pos] = y; shz[pos] = z; sp16[pos] = (uint16_t)p;
        }
        __syncthreads();

        float lox = 1e30f, loy = 1e30f, loz = 1e30f;
        float hix = -1e30f, hiy = -1e30f, hiz = -1e30f;
        float dist[16];
        unsigned origs[16];
        unsigned invp[8];
#pragma unroll
        for (int j = 0; j < 16; j++) {
            float x = shx[tid * 16 + j], y = shy[tid * 16 + j], z = shz[tid * 16 + j];
            lox = fminf(lox, x); hix = fmaxf(hix, x);
            loy = fminf(loy, y); hiy = fmaxf(hiy, y);
            loz = fminf(loz, z); hiz = fmaxf(hiz, z);
            dist[j] = 10000000000.0f;
            origs[j] = (unsigned)sp16[tid * 16 + j];
            unsigned iv = 16383u - origs[j];
            if ((j & 1) == 0) invp[j >> 1] = iv;
            else              invp[j >> 1] |= iv << 16;
        }
        __syncthreads();
        // perm keyed by inverse orig: sp16[16383-orig] = sorted pos
#pragma unroll
        for (int j = 0; j < 16; j++) sp16[16383u - origs[j]] = (uint16_t)(tid * 16 + j);
        __syncthreads();

        unsigned myHi = 0x7f800000u, myLo = 0u;
        float wx = xb[0], wy = xb[1], wz = xb[2];

        const float4* px4 = (const float4*)shx + tid * 4;
        const float4* py4 = (const float4*)shy + tid * 4;
        const float4* pz4 = (const float4*)shz + tid * 4;
        const int lane = tid & 31, wrp = tid >> 5;

        for (int k = 0; k < NCTR; k++) {
            if (tid == 0) {
                outx[3 * k]     = wx;
                outx[3 * k + 1] = wy;
                outx[3 * k + 2] = wz;
                if ((k & 7) == 7) {
                    unsigned pv = (unsigned)(k + 1);
                    asm volatile("st.release.gpu.u32 [%0], %1;"
                                 :: "l"(&g_progress[b]), "r"(pv) : "memory");
                }
            }
            if (k == NCTR - 1) break;

            float lbx = fmaxf(0.0f, fmaxf(lox - wx, wx - hix));
            float lby = fmaxf(0.0f, fmaxf(loy - wy, wy - hiy));
            float lbz = fmaxf(0.0f, fmaxf(loz - wz, wz - hiz));
            float lb2 = lbx * lbx + lby * lby + lbz * lbz;
            bool re = !(lb2 * 0.99999f > __uint_as_float(myHi));

            if (re) {
                unsigned long long nk = 0;
                const unsigned long long nwx2 = pack2(-wx, -wx);
                const unsigned long long nwy2 = pack2(-wy, -wy);
                const unsigned long long nwz2 = pack2(-wz, -wz);
#pragma unroll
                for (int q = 0; q < 4; q++) {
                    float4 xv = px4[q], yv = py4[q], zv = pz4[q];
#pragma unroll
                    for (int h = 0; h < 2; h++) {
                        unsigned long long xp = (h == 0) ? pack2(xv.x, xv.y) : pack2(xv.z, xv.w);
                        unsigned long long yp = (h == 0) ? pack2(yv.x, yv.y) : pack2(yv.z, yv.w);
                        unsigned long long zp = (h == 0) ? pack2(zv.x, zv.y) : pack2(zv.z, zv.w);
                        unsigned long long dxp = add2(xp, nwx2);
                        unsigned long long dyp = add2(yp, nwy2);
                        unsigned long long dzp = add2(zp, nwz2);
                        unsigned long long dd =
                            add2(add2(mul2(dxp, dxp), mul2(dyp, dyp)), mul2(dzp, dzp));
                        float dlo, dhi;
                        unpack2(dd, dlo, dhi);
                        const int j = q * 4 + h * 2;
                        float nd0 = fminf(dist[j],     dlo);
                        float nd1 = fminf(dist[j + 1], dhi);
                        dist[j] = nd0; dist[j + 1] = nd1;
                        unsigned pr = invp[j >> 1];
                        unsigned long long pk0 =
                            ((unsigned long long)__float_as_uint(nd0) << 32) | (pr & 0xffffu);
                        unsigned long long pk1 =
                            ((unsigned long long)__float_as_uint(nd1) << 32) | (pr >> 16);
                        if (pk0 > nk) nk = pk0;
                        if (pk1 > nk) nk = pk1;
                    }
                }
                myHi = (unsigned)(nk >> 32); myLo = (unsigned)nk;
            }

            // warp-best, one STS64 per warp
            unsigned wm = __reduce_max_sync(0xffffffffu, myHi);
            unsigned cand = (myHi == wm) ? myLo : 0u;
            unsigned im = __reduce_max_sync(0xffffffffu, cand);
            if (lane == 0)
                wkey[wrp] = ((unsigned long long)wm << 32) | im;
            __syncthreads();

            // warp0 derives the global winner and publishes coords
            if (tid < 32) {
                unsigned long long v = wkey[lane];
                unsigned vh = (unsigned)(v >> 32), vl = (unsigned)v;
                unsigned gh = __reduce_max_sync(0xffffffffu, vh);
                unsigned cand2 = (vh == gh) ? vl : 0u;
                unsigned gl = __reduce_max_sync(0xffffffffu, cand2);
                if (vh == gh && vl == gl) {             // unique winning slot
                    unsigned pos = (unsigned)sp16[gl];
                    *s_win = make_float4(shx[pos], shy[pos], shz[pos], 0.0f);
                }
            }
            __syncthreads();

            float4 wv = *s_win;                          // broadcast LDS128
            wx = wv.x; wy = wv.y; wz = wv.z;
        }
        return;
    }

    // ===================== worker path =====================
    const int w = blockIdx.x - NB;
    float* W1s = sm + WOW1;
    float* W2s = sm + WOW2;
    float* W3s = sm + WOW3;
    float* sv  = sm + WOSV;
    int* pooled = (int*)(sm + WOPOOL);
    int* sidx   = (int*)(sm + WOSIDX);

    for (int e = t; e < 68 * 64; e += 1024) {
        int j = e >> 6, o = e & 63;
        float v = (j < 64) ? W1[o * 67 + 3 + j] : (j < 67 ? W1[o * 67 + (j - 64)] : 0.0f);
        W1s[j * 64 + o] = v;
    }
    for (int e = t; e < 64 * 64; e += 1024) {
        int i = e >> 6, o = e & 63;
        W2s[i * 64 + o] = W2[o * 64 + i];
    }
    for (int e = t; e < 64 * 128; e += 1024) {
        int i = e >> 7, o = e & 127;
        W3s[i * 128 + o] = W3[o * 64 + i];
    }
    if (t < 64) { sv[t] = s1[t]; sv[64 + t] = b1[t]; sv[128 + t] = s2[t]; sv[192 + t] = b2[t]; }
    if (t < 128) { sv[256 + t] = s3[t]; sv[384 + t] = b3[t]; }

    const int sub = t >> 8, tl = t & 255;
    float* bA = sm + WOBA + sub * 64 * BUFW;
    float* bB = sm + WOBB + sub * 64 * BUFW;
    int* mypool = pooled + sub * 256;
    const int sg = tl >> 4, og = tl & 15;
    const int wid = t >> 5, lane = t & 31;

    for (int g = w; g < NGROUP; g += NWORK) {
        const int b  = g & 3;
        const int j0 = (g >> 2) * 8;

        if (t == 0) {
            unsigned pv;
            for (;;) {
                asm volatile("ld.acquire.gpu.u32 %0, [%1];"
                             : "=r"(pv) : "l"(&g_progress[b]) : "memory");
                if (pv >= (unsigned)(j0 + 8)) break;
                __nanosleep(128);
            }
        }
        pooled[t] = 0;
        __syncthreads();

        if (wid < 8) {
            const int j = j0 + wid;
            const float* xb2 = xyz + (size_t)b * NPTS * 3;
            const float* cp = out + ((size_t)b * NCTR + j) * 3;
            float cx = cp[0], cy = cp[1], cz = cp[2];
            int cnt = 0, firstidx = 0;
            for (int c = 0; c < NPTS / 32 && cnt < NSAMP; ++c) {
                int p = c * 32 + lane;
                float x = xb2[3 * p], y = xb2[3 * p + 1], z = xb2[3 * p + 2];
                float dx = __fsub_rn(cx, x), dy = __fsub_rn(cy, y), dz = __fsub_rn(cz, z);
                float d2 = __fadd_rn(__fadd_rn(__fmul_rn(dx, dx), __fmul_rn(dy, dy)),
                                     __fmul_rn(dz, dz));
                bool in = d2 < R2;
                unsigned m = __ballot_sync(0xffffffffu, in);
                if (m) {
                    if (cnt == 0)
                        firstidx = __shfl_sync(0xffffffffu, p, __ffs(m) - 1);
                    int rank = cnt + __popc(m & ((1u << lane) - 1u));
                    if (in && rank < NSAMP) sidx[wid * 32 + rank] = p;
                    cnt += __popc(m);
                }
            }
            if (cnt < NSAMP && lane >= cnt) sidx[wid * 32 + lane] = firstidx;
        }
        __syncthreads();

        {
            int s = tl & 63, part = tl >> 6;
            int sglob = sub * 64 + s;
            int j = j0 + (sglob >> 5);
            int pi = sidx[sglob];
            const float4* frow = (const float4*)(g_featsT + ((size_t)b * NPTS + pi) * 64);
            float4* dst4 = (float4*)(bA + s * BUFW);
#pragma unroll
            for (int f = 0; f < 4; ++f) dst4[part * 4 + f] = frow[part * 4 + f];
            if (part == 0) {
                const float* cp = out + ((size_t)b * NCTR + j) * 3;
                const float* prr = xyz + ((size_t)b * NPTS + pi) * 3;
                bA[s * BUFW + 64] = prr[0] - cp[0];
                bA[s * BUFW + 65] = prr[1] - cp[1];
                bA[s * BUFW + 66] = prr[2] - cp[2];
                bA[s * BUFW + 67] = 0.0f;
            }
        }
        __syncthreads();

        {   // Layer 1: K=68 padded
            float acc[4][4];
#pragma unroll
            for (int si = 0; si < 4; ++si)
#pragma unroll
                for (int oj = 0; oj < 4; ++oj) acc[si][oj] = 0.0f;
            const float4* a0 = (const float4*)(bA + (sg     ) * BUFW);
            const float4* a1 = (const float4*)(bA + (sg + 16) * BUFW);
            const float4* a2 = (const float4*)(bA + (sg + 32) * BUFW);
            const float4* a3 = (const float4*)(bA + (sg + 48) * BUFW);
#pragma unroll
            for (int kk = 0; kk < 17; ++kk) {
                float4 v0 = a0[kk], v1 = a1[kk], v2 = a2[kk], v3 = a3[kk];
                float va0[4] = {v0.x, v0.y, v0.z, v0.w};
                float va1[4] = {v1.x, v1.y, v1.z, v1.w};
                float va2[4] = {v2.x, v2.y, v2.z, v2.w};
                float va3[4] = {v3.x, v3.y, v3.z, v3.w};
#pragma unroll
                for (int j = 0; j < 4; ++j) {
                    float4 wv4 = *(const float4*)(W1s + (kk * 4 + j) * 64 + og * 4);
                    float wv[4] = {wv4.x, wv4.y, wv4.z, wv4.w};
#pragma unroll
                    for (int oj = 0; oj < 4; ++oj) {
                        acc[0][oj] = fmaf(va0[j], wv[oj], acc[0][oj]);
                        acc[1][oj] = fmaf(va1[j], wv[oj], acc[1][oj]);
                        acc[2][oj] = fmaf(va2[j], wv[oj], acc[2][oj]);
                        acc[3][oj] = fmaf(va3[j], wv[oj], acc[3][oj]);
                    }
                }
            }
#pragma unroll
            for (int si = 0; si < 4; ++si) {
                float4 r;
                int o0 = og * 4;
                r.x = fmaxf(fmaf(acc[si][0], sv[o0],     sv[64 + o0]),     0.0f);
                r.y = fmaxf(fmaf(acc[si][1], sv[o0 + 1], sv[64 + o0 + 1]), 0.0f);
                r.z = fmaxf(fmaf(acc[si][2], sv[o0 + 2], sv[64 + o0 + 2]), 0.0f);
                r.w = fmaxf(fmaf(acc[si][3], sv[o0 + 3], sv[64 + o0 + 3]), 0.0f);
                *(float4*)(bB + (sg + 16 * si) * BUFW + o0) = r;
            }
        }
        __syncthreads();

        {   // Layer 2: K=64
            float acc[4][4];
#pragma unroll
            for (int si = 0; si < 4; ++si)
#pragma unroll
                for (int oj = 0; oj < 4; ++oj) acc[si][oj] = 0.0f;
            const float4* a0 = (const float4*)(bB + (sg     ) * BUFW);
            const float4* a1 = (const float4*)(bB + (sg + 16) * BUFW);
            const float4* a2 = (const float4*)(bB + (sg + 32) * BUFW);
            const float4* a3 = (const float4*)(bB + (sg + 48) * BUFW);
#pragma unroll
            for (int kk = 0; kk < 16; ++kk) {
                float4 v0 = a0[kk], v1 = a1[kk], v2 = a2[kk], v3 = a3[kk];
                float va0[4] = {v0.x, v0.y, v0.z, v0.w};
                float va1[4] = {v1.x, v1.y, v1.z, v1.w};
                float va2[4] = {v2.x, v2.y, v2.z, v2.w};
                float va3[4] = {v3.x, v3.y, v3.z, v3.w};
#pragma unroll
                for (int j = 0; j < 4; ++j) {
                    float4 wv4 = *(const float4*)(W2s + (kk * 4 + j) * 64 + og * 4);
                    float wv[4] = {wv4.x, wv4.y, wv4.z, wv4.w};
#pragma unroll
                    for (int oj = 0; oj < 4; ++oj) {
                        acc[0][oj] = fmaf(va0[j], wv[oj], acc[0][oj]);
                        acc[1][oj] = fmaf(va1[j], wv[oj], acc[1][oj]);
                        acc[2][oj] = fmaf(va2[j], wv[oj], acc[2][oj]);
                        acc[3][oj] = fmaf(va3[j], wv[oj], acc[3][oj]);
                    }
                }
            }
#pragma unroll
            for (int si = 0; si < 4; ++si) {
                float4 r;
                int o0 = og * 4;
                r.x = fmaxf(fmaf(acc[si][0], sv[128 + o0],     sv[192 + o0]),     0.0f);
                r.y = fmaxf(fmaf(acc[si][1], sv[128 + o0 + 1], sv[192 + o0 + 1]), 0.0f);
                r.z = fmaxf(fmaf(acc[si][2], sv[128 + o0 + 2], sv[192 + o0 + 2]), 0.0f);
                r.w = fmaxf(fmaf(acc[si][3], sv[128 + o0 + 3], sv[192 + o0 + 3]), 0.0f);
                *(float4*)(bA + (sg + 16 * si) * BUFW + o0) = r;
            }
        }
        __syncthreads();

        {   // Layer 3: K=64, 128 outs in 2 passes, fused maxpool
            const float4* a0 = (const float4*)(bA + (sg     ) * BUFW);
            const float4* a1 = (const float4*)(bA + (sg + 16) * BUFW);
            const float4* a2 = (const float4*)(bA + (sg + 32) * BUFW);
            const float4* a3 = (const float4*)(bA + (sg + 48) * BUFW);
#pragma unroll
            for (int pass = 0; pass < 2; ++pass) {
                const int o0 = og * 4 + pass * 64;
                float acc[4][4];
#pragma unroll
                for (int si = 0; si < 4; ++si)
#pragma unroll
                    for (int oj = 0; oj < 4; ++oj) acc[si][oj] = 0.0f;
#pragma unroll
                for (int kk = 0; kk < 16; ++kk) {
                    float4 v0 = a0[kk], v1 = a1[kk], v2 = a2[kk], v3 = a3[kk];
                    float va0[4] = {v0.x, v0.y, v0.z, v0.w};
                    float va1[4] = {v1.x, v1.y, v1.z, v1.w};
                    float va2[4] = {v2.x, v2.y, v2.z, v2.w};
                    float va3[4] = {v3.x, v3.y, v3.z, v3.w};
#pragma unroll
                    for (int j = 0; j < 4; ++j) {
                        float4 wv4 = *(const float4*)(W3s + (kk * 4 + j) * 128 + o0);
                        float wv[4] = {wv4.x, wv4.y, wv4.z, wv4.w};
#pragma unroll
                        for (int oj = 0; oj < 4; ++oj) {
                            acc[0][oj] = fmaf(va0[j], wv[oj], acc[0][oj]);
                            acc[1][oj] = fmaf(va1[j], wv[oj], acc[1][oj]);
                            acc[2][oj] = fmaf(va2[j], wv[oj], acc[2][oj]);
                            acc[3][oj] = fmaf(va3[j], wv[oj], acc[3][oj]);
                        }
                    }
                }
#pragma unroll
                for (int oj = 0; oj < 4; ++oj) {
                    int o = o0 + oj;
                    float sc = sv[256 + o], bi = sv[384 + o];
                    float y0 = fmaxf(fmaf(acc[0][oj], sc, bi), 0.0f);
                    float y1 = fmaxf(fmaf(acc[1][oj], sc, bi), 0.0f);
                    float y2 = fmaxf(fmaf(acc[2][oj], sc, bi), 0.0f);
                    float y3 = fmaxf(fmaf(acc[3][oj], sc, bi), 0.0f);
                    atomicMax(&mypool[o],       __float_as_int(fmaxf(y0, y1)));
                    atomicMax(&mypool[128 + o], __float_as_int(fmaxf(y2, y3)));
                }
            }
        }
        __syncthreads();

        {
            int cc = t >> 7, o = t & 127;
            out[12288 + ((size_t)b * 128 + o) * NCTR + (j0 + cc)] = __int_as_float(pooled[t]);
        }
        __syncthreads();
    }
}

// ---------------------------------------------------------------------------
extern "C" void kernel_launch(void* const* d_in, const int* in_sizes, int n_in,
                              void* d_out, int out_size)
{
    const float* xyz      = (const float*)d_in[0];
    const float* features = (const float*)d_in[1];
    const float* W1 = (const float*)d_in[2];
    const float* s1 = (const float*)d_in[3];
    const float* b1 = (const float*)d_in[4];
    const float* W2 = (const float*)d_in[5];
    const float* s2 = (const float*)d_in[6];
    const float* b2 = (const float*)d_in[7];
    const float* W3 = (const float*)d_in[8];
    const float* s3 = (const float*)d_in[9];
    const float* b3 = (const float*)d_in[10];
    float* out = (float*)d_out;

    cudaFuncSetAttribute(fused_kernel, cudaFuncAttributeMaxDynamicSharedMemorySize,
                         FPS_SMEM);

    reset_kernel<<<1, 32>>>();
    transpose_kernel<<<dim3(NPTS / 32, 2, NB), dim3(32, 8)>>>(features);
    fused_kernel<<<NGRID, 1024, FPS_SMEM>>>(
        xyz, W1, s1, b1, W2, s2, b2, W3, s3, b3, out);
}

// round 17
// speedup vs baseline: 1.1056x; 1.1056x over previous
#include <cuda_runtime.h>
#include <cuda_bf16.h>
#include <stdint.h>

#define NB    4
#define NPTS  16384
#define NCTR  1024
#define NSAMP 32
#define R2    0.04f
#define NWORK 124
#define NGRID (NB + NWORK)      // 128 blocks <= 148 SMs, 1/SM @ 226KB smem
#define NGROUP (NB * NCTR / 8)  // 512 groups of 8 centers

// ---------------- scratch (no allocations allowed) ----------------
__device__ float    g_featsT[(size_t)NB * NPTS * 64];   // (B,N,C)
__device__ unsigned g_progress[NB];

// ---------------- packed f32x2 helpers (exact per-half RN) ----------------
__device__ __forceinline__ unsigned long long pack2(float lo, float hi) {
    unsigned long long r;
    asm("mov.b64 %0, {%1, %2};" : "=l"(r) : "f"(lo), "f"(hi));
    return r;
}
__device__ __forceinline__ void unpack2(unsigned long long v, float& lo, float& hi) {
    asm("mov.b64 {%0, %1}, %2;" : "=f"(lo), "=f"(hi) : "l"(v));
}
__device__ __forceinline__ unsigned long long add2(unsigned long long a, unsigned long long b) {
    unsigned long long r;
    asm("add.rn.f32x2 %0, %1, %2;" : "=l"(r) : "l"(a), "l"(b));
    return r;
}
__device__ __forceinline__ unsigned long long mul2(unsigned long long a, unsigned long long b) {
    unsigned long long r;
    asm("mul.rn.f32x2 %0, %1, %2;" : "=l"(r) : "l"(a), "l"(b));
    return r;
}

// Morton cell index from 3-bit coords: warp-compact 2x2x4 cell footprints.
__device__ __forceinline__ unsigned morton3(unsigned cx, unsigned cy, unsigned cz)
{
    unsigned m = 0;
#pragma unroll
    for (int i = 0; i < 3; i++) {
        m |= ((cx >> i) & 1u) << (3 * i + 2);
        m |= ((cy >> i) & 1u) << (3 * i + 1);
        m |= ((cz >> i) & 1u) << (3 * i);
    }
    return m;
}

// ---------------- layouts ----------------
#define FPS_CTRL_OFF (3 * NPTS * 4 + NPTS * 2)   // bytes
#define FPS_SMEM     (FPS_CTRL_OFF + 2048)       // 231424 B

#define BUFW 68
#define WOW1   0
#define WOW2   (WOW1 + 68 * 64)
#define WOW3   (WOW2 + 64 * 64)
#define WOSV   (WOW3 + 64 * 128)
#define WOBA   (WOSV + 512)
#define WOBB   (WOBA + 4 * 64 * BUFW)
#define WOPOOL (WOBB + 4 * 64 * BUFW)
#define WOSIDX (WOPOOL + 1024)   // 256 ints; total 53248 floats = 212992 B

__global__ void reset_kernel()
{
    if (threadIdx.x < NB) g_progress[threadIdx.x] = 0u;
}

// ---------------------------------------------------------------------------
// transpose features (B,64,N) -> (B,N,64)
// ---------------------------------------------------------------------------
__global__ void transpose_kernel(const float* __restrict__ f)
{
    __shared__ float tile[32][33];
    int n0 = blockIdx.x * 32, c0 = blockIdx.y * 32, b = blockIdx.z;
    int tx = threadIdx.x, ty = threadIdx.y;
    const float* src = f + (size_t)b * 64 * NPTS;
#pragma unroll
    for (int r = 0; r < 32; r += 8)
        tile[ty + r][tx] = src[(size_t)(c0 + ty + r) * NPTS + n0 + tx];
    __syncthreads();
    float* dst = g_featsT + (size_t)b * NPTS * 64;
#pragma unroll
    for (int r = 0; r < 32; r += 8)
        dst[(size_t)(n0 + ty + r) * 64 + c0 + tx] = tile[tx][ty + r];
}

// ---------------------------------------------------------------------------
// Fused persistent kernel:
//   blocks 0..3   : FPS (1 per batch) + release-store progress every 8 ctrs
//   blocks 4..127 : per-group {acquire-spin, ballquery, MLP, pool, store}
// FPS: Morton-sorted cells (warp-coherent pruning), exact thread-bbox prune,
// single barrier/iter, all-warp redux reduction (validated R13 form),
// double-buffered warp-key slots wk[k&1][32].
// ---------------------------------------------------------------------------
__global__ void __launch_bounds__(1024, 1)
fused_kernel(const float* __restrict__ xyz,
             const float* __restrict__ W1, const float* __restrict__ s1, const float* __restrict__ b1,
             const float* __restrict__ W2, const float* __restrict__ s2, const float* __restrict__ b2,
             const float* __restrict__ W3, const float* __restrict__ s3, const float* __restrict__ b3,
             float* __restrict__ out)
{
    extern __shared__ float sm[];
    const int t = threadIdx.x;

    if (blockIdx.x < NB) {
        // ================= FPS path =================
        float* shx = sm;
        float* shy = sm + NPTS;
        float* shz = sm + 2 * NPTS;
        uint16_t* sp16 = (uint16_t*)(sm + 3 * NPTS);
        unsigned int* ctrl = (unsigned int*)((char*)sm + FPS_CTRL_OFF);
        unsigned int* hist = ctrl;                                 // setup only
        unsigned long long* wk = (unsigned long long*)ctrl;        // [2][32] aliases hist

        const int tid = t;
        const int b = blockIdx.x;
        const float* xb = xyz + (size_t)b * NPTS * 3;
        float* outx = out + (size_t)b * NCTR * 3;

        if (tid < 512) hist[tid] = 0u;
        __syncthreads();
        for (int p = tid; p < NPTS; p += 1024) {
            float x = xb[3 * p], y = xb[3 * p + 1], z = xb[3 * p + 2];
            unsigned cx = min(7, (int)(x * 8.0f));
            unsigned cy = min(7, (int)(y * 8.0f));
            unsigned cz = min(7, (int)(z * 8.0f));
            atomicAdd(&hist[morton3(cx, cy, cz)], 1u);
        }
        __syncthreads();
        if (tid < 32) {
            unsigned v[16], s = 0;
#pragma unroll
            for (int i = 0; i < 16; i++) { v[i] = hist[tid * 16 + i]; s += v[i]; }
            unsigned run = s;
#pragma unroll
            for (int o = 1; o < 32; o <<= 1) {
                unsigned t2 = __shfl_up_sync(0xffffffffu, run, o);
                if (tid >= o) run += t2;
            }
            unsigned acc = run - s;
#pragma unroll
            for (int i = 0; i < 16; i++) { unsigned c = v[i]; hist[tid * 16 + i] = acc; acc += c; }
        }
        __syncthreads();
        for (int p = tid; p < NPTS; p += 1024) {
            float x = xb[3 * p], y = xb[3 * p + 1], z = xb[3 * p + 2];
            unsigned cx = min(7, (int)(x * 8.0f));
            unsigned cy = min(7, (int)(y * 8.0f));
            unsigned cz = min(7, (int)(z * 8.0f));
            unsigned pos = atomicAdd(&hist[morton3(cx, cy, cz)], 1u);
            shx[pos] = x; shy[pos] = y; shz[pos] = z; sp16[pos] = (uint16_t)p;
        }
        __syncthreads();

        float lox = 1e30f, loy = 1e30f, loz = 1e30f;
        float hix = -1e30f, hiy = -1e30f, hiz = -1e30f;
        float dist[16];
        unsigned origs[16];
        unsigned invp[8];
#pragma unroll
        for (int j = 0; j < 16; j++) {
            float x = shx[tid * 16 + j], y = shy[tid * 16 + j], z = shz[tid * 16 + j];
            lox = fminf(lox, x); hix = fmaxf(hix, x);
            loy = fminf(loy, y); hiy = fmaxf(hiy, y);
            loz = fminf(loz, z); hiz = fmaxf(hiz, z);
            dist[j] = 10000000000.0f;
            origs[j] = (unsigned)sp16[tid * 16 + j];
            unsigned iv = 16383u - origs[j];
            if ((j & 1) == 0) invp[j >> 1] = iv;
            else              invp[j >> 1] |= iv << 16;
        }
        __syncthreads();
        // perm keyed by inverse orig: sp16[16383-orig] = sorted pos
#pragma unroll
        for (int j = 0; j < 16; j++) sp16[16383u - origs[j]] = (uint16_t)(tid * 16 + j);
        __syncthreads();

        unsigned myHi = 0x7f800000u, myLo = 0u;
        float wx = xb[0], wy = xb[1], wz = xb[2];

        const float4* px4 = (const float4*)shx + tid * 4;
        const float4* py4 = (const float4*)shy + tid * 4;
        const float4* pz4 = (const float4*)shz + tid * 4;
        const int lane = tid & 31, wrp = tid >> 5;

        for (int k = 0; k < NCTR; k++) {
            if (tid == 0) {
                outx[3 * k]     = wx;
                outx[3 * k + 1] = wy;
                outx[3 * k + 2] = wz;
                if ((k & 7) == 7) {
                    unsigned pv = (unsigned)(k + 1);
                    asm volatile("st.release.gpu.u32 [%0], %1;"
                                 :: "l"(&g_progress[b]), "r"(pv) : "memory");
                }
            }
            if (k == NCTR - 1) break;

            float lbx = fmaxf(0.0f, fmaxf(lox - wx, wx - hix));
            float lby = fmaxf(0.0f, fmaxf(loy - wy, wy - hiy));
            float lbz = fmaxf(0.0f, fmaxf(loz - wz, wz - hiz));
            float lb2 = lbx * lbx + lby * lby + lbz * lbz;
            bool re = !(lb2 * 0.99999f > __uint_as_float(myHi));

            if (re) {
                unsigned long long nk = 0;
                const unsigned long long nwx2 = pack2(-wx, -wx);
                const unsigned long long nwy2 = pack2(-wy, -wy);
                const unsigned long long nwz2 = pack2(-wz, -wz);
#pragma unroll
                for (int q = 0; q < 4; q++) {
                    float4 xv = px4[q], yv = py4[q], zv = pz4[q];
#pragma unroll
                    for (int h = 0; h < 2; h++) {
                        unsigned long long xp = (h == 0) ? pack2(xv.x, xv.y) : pack2(xv.z, xv.w);
                        unsigned long long yp = (h == 0) ? pack2(yv.x, yv.y) : pack2(yv.z, yv.w);
                        unsigned long long zp = (h == 0) ? pack2(zv.x, zv.y) : pack2(zv.z, zv.w);
                        unsigned long long dxp = add2(xp, nwx2);
                        unsigned long long dyp = add2(yp, nwy2);
                        unsigned long long dzp = add2(zp, nwz2);
                        unsigned long long dd =
                            add2(add2(mul2(dxp, dxp), mul2(dyp, dyp)), mul2(dzp, dzp));
                        float dlo, dhi;
                        unpack2(dd, dlo, dhi);
                        const int j = q * 4 + h * 2;
                        float nd0 = fminf(dist[j],     dlo);
                        float nd1 = fminf(dist[j + 1], dhi);
                        dist[j] = nd0; dist[j + 1] = nd1;
                        unsigned pr = invp[j >> 1];
                        unsigned long long pk0 =
                            ((unsigned long long)__float_as_uint(nd0) << 32) | (pr & 0xffffu);
                        unsigned long long pk1 =
                            ((unsigned long long)__float_as_uint(nd1) << 32) | (pr >> 16);
                        if (pk0 > nk) nk = pk0;
                        if (pk1 > nk) nk = pk1;
                    }
                }
                myHi = (unsigned)(nk >> 32); myLo = (unsigned)nk;
            }

            // ---- warp reduce: unconditional redux (cached bests always valid)
            unsigned wm = __reduce_max_sync(0xffffffffu, myHi);
            unsigned cand = (myHi == wm) ? myLo : 0u;
            unsigned im = __reduce_max_sync(0xffffffffu, cand);
            const int ph = k & 1;
            if (lane == 0)
                wk[ph * 32 + wrp] = ((unsigned long long)wm << 32) | im;
            __syncthreads();

            // ---- every warp computes the global winner (no 2nd barrier) ----
            unsigned long long v = wk[ph * 32 + lane];
            unsigned vh = (unsigned)(v >> 32), vl = (unsigned)v;
            unsigned gh = __reduce_max_sync(0xffffffffu, vh);
            unsigned cand2 = (vh == gh) ? vl : 0u;
            unsigned gl = __reduce_max_sync(0xffffffffu, cand2);
            unsigned pos = (unsigned)sp16[gl];
            wx = shx[pos]; wy = shy[pos]; wz = shz[pos];
        }
        return;
    }

    // ===================== worker path =====================
    const int w = blockIdx.x - NB;
    float* W1s = sm + WOW1;
    float* W2s = sm + WOW2;
    float* W3s = sm + WOW3;
    float* sv  = sm + WOSV;
    int* pooled = (int*)(sm + WOPOOL);
    int* sidx   = (int*)(sm + WOSIDX);

    for (int e = t; e < 68 * 64; e += 1024) {
        int j = e >> 6, o = e & 63;
        float v = (j < 64) ? W1[o * 67 + 3 + j] : (j < 67 ? W1[o * 67 + (j - 64)] : 0.0f);
        W1s[j * 64 + o] = v;
    }
    for (int e = t; e < 64 * 64; e += 1024) {
        int i = e >> 6, o = e & 63;
        W2s[i * 64 + o] = W2[o * 64 + i];
    }
    for (int e = t; e < 64 * 128; e += 1024) {
        int i = e >> 7, o = e & 127;
        W3s[i * 128 + o] = W3[o * 64 + i];
    }
    if (t < 64) { sv[t] = s1[t]; sv[64 + t] = b1[t]; sv[128 + t] = s2[t]; sv[192 + t] = b2[t]; }
    if (t < 128) { sv[256 + t] = s3[t]; sv[384 + t] = b3[t]; }

    const int sub = t >> 8, tl = t & 255;
    float* bA = sm + WOBA + sub * 64 * BUFW;
    float* bB = sm + WOBB + sub * 64 * BUFW;
    int* mypool = pooled + sub * 256;
    const int sg = tl >> 4, og = tl & 15;
    const int wid = t >> 5, lane = t & 31;

    for (int g = w; g < NGROUP; g += NWORK) {
        const int b  = g & 3;
        const int j0 = (g >> 2) * 8;

        if (t == 0) {
            unsigned pv;
            for (;;) {
                asm volatile("ld.acquire.gpu.u32 %0, [%1];"
                             : "=r"(pv) : "l"(&g_progress[b]) : "memory");
                if (pv >= (unsigned)(j0 + 8)) break;
                __nanosleep(128);
            }
        }
        pooled[t] = 0;
        __syncthreads();

        if (wid < 8) {
            const int j = j0 + wid;
            const float* xb2 = xyz + (size_t)b * NPTS * 3;
            const float* cp = out + ((size_t)b * NCTR + j) * 3;
            float cx = cp[0], cy = cp[1], cz = cp[2];
            int cnt = 0, firstidx = 0;
            for (int c = 0; c < NPTS / 32 && cnt < NSAMP; ++c) {
                int p = c * 32 + lane;
                float x = xb2[3 * p], y = xb2[3 * p + 1], z = xb2[3 * p + 2];
                float dx = __fsub_rn(cx, x), dy = __fsub_rn(cy, y), dz = __fsub_rn(cz, z);
                float d2 = __fadd_rn(__fadd_rn(__fmul_rn(dx, dx), __fmul_rn(dy, dy)),
                                     __fmul_rn(dz, dz));
                bool in = d2 < R2;
                unsigned m = __ballot_sync(0xffffffffu, in);
                if (m) {
                    if (cnt == 0)
                        firstidx = __shfl_sync(0xffffffffu, p, __ffs(m) - 1);
                    int rank = cnt + __popc(m & ((1u << lane) - 1u));
                    if (in && rank < NSAMP) sidx[wid * 32 + rank] = p;
                    cnt += __popc(m);
                }
            }
            if (cnt < NSAMP && lane >= cnt) sidx[wid * 32 + lane] = firstidx;
        }
        __syncthreads();

        {
            int s = tl & 63, part = tl >> 6;
            int sglob = sub * 64 + s;
            int j = j0 + (sglob >> 5);
            int pi = sidx[sglob];
            const float4* frow = (const float4*)(g_featsT + ((size_t)b * NPTS + pi) * 64);
            float4* dst4 = (float4*)(bA + s * BUFW);
#pragma unroll
            for (int f = 0; f < 4; ++f) dst4[part * 4 + f] = frow[part * 4 + f];
            if (part == 0) {
                const float* cp = out + ((size_t)b * NCTR + j) * 3;
                const float* prr = xyz + ((size_t)b * NPTS + pi) * 3;
                bA[s * BUFW + 64] = prr[0] - cp[0];
                bA[s * BUFW + 65] = prr[1] - cp[1];
                bA[s * BUFW + 66] = prr[2] - cp[2];
                bA[s * BUFW + 67] = 0.0f;
            }
        }
        __syncthreads();

        {   // Layer 1: K=68 padded
            float acc[4][4];
#pragma unroll
            for (int si = 0; si < 4; ++si)
#pragma unroll
                for (int oj = 0; oj < 4; ++oj) acc[si][oj] = 0.0f;
            const float4* a0 = (const float4*)(bA + (sg     ) * BUFW);
            const float4* a1 = (const float4*)(bA + (sg + 16) * BUFW);
            const float4* a2 = (const float4*)(bA + (sg + 32) * BUFW);
            const float4* a3 = (const float4*)(bA + (sg + 48) * BUFW);
#pragma unroll
            for (int kk = 0; kk < 17; ++kk) {
                float4 v0 = a0[kk], v1 = a1[kk], v2 = a2[kk], v3 = a3[kk];
                float va0[4] = {v0.x, v0.y, v0.z, v0.w};
                float va1[4] = {v1.x, v1.y, v1.z, v1.w};
                float va2[4] = {v2.x, v2.y, v2.z, v2.w};
                float va3[4] = {v3.x, v3.y, v3.z, v3.w};
#pragma unroll
                for (int j = 0; j < 4; ++j) {
                    float4 wv4 = *(const float4*)(W1s + (kk * 4 + j) * 64 + og * 4);
                    float wv[4] = {wv4.x, wv4.y, wv4.z, wv4.w};
#pragma unroll
                    for (int oj = 0; oj < 4; ++oj) {
                        acc[0][oj] = fmaf(va0[j], wv[oj], acc[0][oj]);
                        acc[1][oj] = fmaf(va1[j], wv[oj], acc[1][oj]);
                        acc[2][oj] = fmaf(va2[j], wv[oj], acc[2][oj]);
                        acc[3][oj] = fmaf(va3[j], wv[oj], acc[3][oj]);
                    }
                }
            }
#pragma unroll
            for (int si = 0; si < 4; ++si) {
                float4 r;
                int o0 = og * 4;
                r.x = fmaxf(fmaf(acc[si][0], sv[o0],     sv[64 + o0]),     0.0f);
                r.y = fmaxf(fmaf(acc[si][1], sv[o0 + 1], sv[64 + o0 + 1]), 0.0f);
                r.z = fmaxf(fmaf(acc[si][2], sv[o0 + 2], sv[64 + o0 + 2]), 0.0f);
                r.w = fmaxf(fmaf(acc[si][3], sv[o0 + 3], sv[64 + o0 + 3]), 0.0f);
                *(float4*)(bB + (sg + 16 * si) * BUFW + o0) = r;
            }
        }
        __syncthreads();

        {   // Layer 2: K=64
            float acc[4][4];
#pragma unroll
            for (int si = 0; si < 4; ++si)
#pragma unroll
                for (int oj = 0; oj < 4; ++oj) acc[si][oj] = 0.0f;
            const float4* a0 = (const float4*)(bB + (sg     ) * BUFW);
            const float4* a1 = (const float4*)(bB + (sg + 16) * BUFW);
            const float4* a2 = (const float4*)(bB + (sg + 32) * BUFW);
            const float4* a3 = (const float4*)(bB + (sg + 48) * BUFW);
#pragma unroll
            for (int kk = 0; kk < 16; ++kk) {
                float4 v0 = a0[kk], v1 = a1[kk], v2 = a2[kk], v3 = a3[kk];
                float va0[4] = {v0.x, v0.y, v0.z, v0.w};
                float va1[4] = {v1.x, v1.y, v1.z, v1.w};
                float va2[4] = {v2.x, v2.y, v2.z, v2.w};
                float va3[4] = {v3.x, v3.y, v3.z, v3.w};
#pragma unroll
                for (int j = 0; j < 4; ++j) {
                    float4 wv4 = *(const float4*)(W2s + (kk * 4 + j) * 64 + og * 4);
                    float wv[4] = {wv4.x, wv4.y, wv4.z, wv4.w};
#pragma unroll
                    for (int oj = 0; oj < 4; ++oj) {
                        acc[0][oj] = fmaf(va0[j], wv[oj], acc[0][oj]);
                        acc[1][oj] = fmaf(va1[j], wv[oj], acc[1][oj]);
                        acc[2][oj] = fmaf(va2[j], wv[oj], acc[2][oj]);
                        acc[3][oj] = fmaf(va3[j], wv[oj], acc[3][oj]);
                    }
                }
            }
#pragma unroll
            for (int si = 0; si < 4; ++si) {
                float4 r;
                int o0 = og * 4;
                r.x = fmaxf(fmaf(acc[si][0], sv[128 + o0],     sv[192 + o0]),     0.0f);
                r.y = fmaxf(fmaf(acc[si][1], sv[128 + o0 + 1], sv[192 + o0 + 1]), 0.0f);
                r.z = fmaxf(fmaf(acc[si][2], sv[128 + o0 + 2], sv[192 + o0 + 2]), 0.0f);
                r.w = fmaxf(fmaf(acc[si][3], sv[128 + o0 + 3], sv[192 + o0 + 3]), 0.0f);
                *(float4*)(bA + (sg + 16 * si) * BUFW + o0) = r;
            }
        }
        __syncthreads();

        {   // Layer 3: K=64, 128 outs in 2 passes, fused maxpool
            const float4* a0 = (const float4*)(bA + (sg     ) * BUFW);
            const float4* a1 = (const float4*)(bA + (sg + 16) * BUFW);
            const float4* a2 = (const float4*)(bA + (sg + 32) * BUFW);
            const float4* a3 = (const float4*)(bA + (sg + 48) * BUFW);
#pragma unroll
            for (int pass = 0; pass < 2; ++pass) {
                const int o0 = og * 4 + pass * 64;
                float acc[4][4];
#pragma unroll
                for (int si = 0; si < 4; ++si)
#pragma unroll
                    for (int oj = 0; oj < 4; ++oj) acc[si][oj] = 0.0f;
#pragma unroll
                for (int kk = 0; kk < 16; ++kk) {
                    float4 v0 = a0[kk], v1 = a1[kk], v2 = a2[kk], v3 = a3[kk];
                    float va0[4] = {v0.x, v0.y, v0.z, v0.w};
                    float va1[4] = {v1.x, v1.y, v1.z, v1.w};
                    float va2[4] = {v2.x, v2.y, v2.z, v2.w};
                    float va3[4] = {v3.x, v3.y, v3.z, v3.w};
#pragma unroll
                    for (int j = 0; j < 4; ++j) {
                        float4 wv4 = *(const float4*)(W3s + (kk * 4 + j) * 128 + o0);
                        float wv[4] = {wv4.x, wv4.y, wv4.z, wv4.w};
#pragma unroll
                        for (int oj = 0; oj < 4; ++oj) {
                            acc[0][oj] = fmaf(va0[j], wv[oj], acc[0][oj]);
                            acc[1][oj] = fmaf(va1[j], wv[oj], acc[1][oj]);
                            acc[2][oj] = fmaf(va2[j], wv[oj], acc[2][oj]);
                            acc[3][oj] = fmaf(va3[j], wv[oj], acc[3][oj]);
                        }
                    }
                }
#pragma unroll
                for (int oj = 0; oj < 4; ++oj) {
                    int o = o0 + oj;
                    float sc = sv[256 + o], bi = sv[384 + o];
                    float y0 = fmaxf(fmaf(acc[0][oj], sc, bi), 0.0f);
                    float y1 = fmaxf(fmaf(acc[1][oj], sc, bi), 0.0f);
                    float y2 = fmaxf(fmaf(acc[2][oj], sc, bi), 0.0f);
                    float y3 = fmaxf(fmaf(acc[3][oj], sc, bi), 0.0f);
                    atomicMax(&mypool[o],       __float_as_int(fmaxf(y0, y1)));
                    atomicMax(&mypool[128 + o], __float_as_int(fmaxf(y2, y3)));
                }
            }
        }
        __syncthreads();

        {
            int cc = t >> 7, o = t & 127;
            out[12288 + ((size_t)b * 128 + o) * NCTR + (j0 + cc)] = __int_as_float(pooled[t]);
        }
        __syncthreads();
    }
}

// ---------------------------------------------------------------------------
extern "C" void kernel_launch(void* const* d_in, const int* in_sizes, int n_in,
                              void* d_out, int out_size)
{
    const float* xyz      = (const float*)d_in[0];
    const float* features = (const float*)d_in[1];
    const float* W1 = (const float*)d_in[2];
    const float* s1 = (const float*)d_in[3];
    const float* b1 = (const float*)d_in[4];
    const float* W2 = (const float*)d_in[5];
    const float* s2 = (const float*)d_in[6];
    const float* b2 = (const float*)d_in[7];
    const float* W3 = (const float*)d_in[8];
    const float* s3 = (const float*)d_in[9];
    const float* b3 = (const float*)d_in[10];
    float* out = (float*)d_out;

    cudaFuncSetAttribute(fused_kernel, cudaFuncAttributeMaxDynamicSharedMemorySize,
                         FPS_SMEM);

    reset_kernel<<<1, 32>>>();
    transpose_kernel<<<dim3(NPTS / 32, 2, NB), dim3(32, 8)>>>(features);
    fused_kernel<<<NGRID, 1024, FPS_SMEM>>>(
        xyz, W1, s1, b1, W2, s2, b2, W3, s3, b3, out);
}